// round 1
// baseline (speedup 1.0000x reference)
#include <cuda_runtime.h>
#include <math.h>
#include <stdint.h>

#define N_NODES 30000
#define N_EDGES 300000
#define N_GRAPHS 256
#define F_NODE 32
#define F_EDGE 16
#define DD 128
#define HH 256
#define NLAYERS 3

#define FLAG_RELU 1
#define FLAG_ADDC 2

// ---------------- scratch (static device allocations; no cudaMalloc) -------
__device__ float g_h[N_NODES * DD];              // node state
__device__ float g_E[(size_t)N_EDGES * 512];     // [Em(256) | Er(256)] per edge (b1 folded in)
__device__ float g_PQ[N_NODES * 1024];           // [Pm|Qm|Pr|Qr] per node
__device__ float g_S[N_NODES * 512];             // [segsum hid_m | segsum hid_r]
__device__ float g_X[N_NODES * 384];             // [agg | ragg | h]
__device__ float g_Hu[N_NODES * HH];             // upd hidden; reused for final gate input g
__device__ float g_gv[N_GRAPHS * DD];
__device__ float g_gv2[N_GRAPHS * DD];
__device__ int   g_degt[N_NODES];
__device__ int   g_degf[N_NODES];
__device__ float g_WE[16 * 512];                 // folded edge-feature weights
__device__ float g_c[512];                       // folded edge bias
__device__ float g_Wcat[128 * 1024];             // [W1m[0:128]|W1m[128:256]|W1r[0:128]|W1r[128:256]]

// ---------------- helpers ---------------------------------------------------
__device__ __forceinline__ void red_add_v4(float* addr, float4 v) {
    asm volatile("red.global.add.v4.f32 [%0], {%1,%2,%3,%4};"
                 :: "l"(addr), "f"(v.x), "f"(v.y), "f"(v.z), "f"(v.w) : "memory");
}

__global__ void zero_k(float4* p, int n4) {
    int i = blockIdx.x * 256 + threadIdx.x;
    if (i < n4) p[i] = make_float4(0.f, 0.f, 0.f, 0.f);
}

// ---------------- weight folding --------------------------------------------
// WE[k][j] = sum_d enc_we[k][d] * W1[(256+d)][jc],  c[j] = sum_d enc_be[d]*W1[256+d][jc] + b1[jc]
__global__ void fold_k(const float* __restrict__ enc_we, const float* __restrict__ enc_be,
                       const float* __restrict__ mw1, const float* __restrict__ mb1,
                       const float* __restrict__ rw1, const float* __restrict__ rb1) {
    int j = threadIdx.x;                       // 0..511
    const float* W1 = (j < 256) ? mw1 : rw1;
    const float* b1 = (j < 256) ? mb1 : rb1;
    int jc = j & 255;
    for (int k = 0; k < 16; k++) {
        float acc = 0.f;
        for (int d = 0; d < 128; d++)
            acc = fmaf(enc_we[k * 128 + d], W1[(256 + d) * 256 + jc], acc);
        g_WE[k * 512 + j] = acc;
    }
    float acc = b1[jc];
    for (int d = 0; d < 128; d++)
        acc = fmaf(enc_be[d], W1[(256 + d) * 256 + jc], acc);
    g_c[j] = acc;
}

__global__ void wcat_k(const float* __restrict__ mw1, const float* __restrict__ rw1) {
    int idx = blockIdx.x * 256 + threadIdx.x;   // 128*1024
    if (idx >= 128 * 1024) return;
    int d = idx >> 10, c = idx & 1023;
    float v;
    if      (c < 256) v = mw1[d * 256 + c];
    else if (c < 512) v = mw1[(128 + d) * 256 + (c - 256)];
    else if (c < 768) v = rw1[d * 256 + (c - 512)];
    else              v = rw1[(128 + d) * 256 + (c - 768)];
    g_Wcat[idx] = v;
}

// ---------------- encoders --------------------------------------------------
__global__ void enc_nodes_k(const float* __restrict__ nf, const float* __restrict__ W,
                            const float* __restrict__ b) {
    __shared__ float Ws[32 * 128];
    __shared__ float bs[128];
    __shared__ float nfs[64][33];
    int tid = threadIdx.x;                      // 256
    for (int i = tid; i < 32 * 128; i += 256) Ws[i] = W[i];
    if (tid < 128) bs[tid] = b[tid];
    int n0 = blockIdx.x * 64;
    for (int i = tid; i < 64 * 32; i += 256) {
        int r = i >> 5, k = i & 31;
        int n = n0 + r;
        nfs[r][k] = (n < N_NODES) ? nf[n * 32 + k] : 0.f;
    }
    __syncthreads();
    int r2 = tid >> 7, j = tid & 127;
    for (int r = r2; r < 64; r += 2) {
        int n = n0 + r;
        if (n >= N_NODES) continue;
        float acc = bs[j];
        #pragma unroll
        for (int k = 0; k < 32; k++) acc = fmaf(nfs[r][k], Ws[k * 128 + j], acc);
        g_h[n * 128 + j] = acc;
    }
}

// E[i][j] = sum_k ef[i][k]*WE[k][j] + c[j]   (j < 512)
__global__ void enc_edges_k(const float* __restrict__ ef) {
    __shared__ float Ws[16 * 512];
    __shared__ float cs[512];
    __shared__ float efs[64][17];
    int tid = threadIdx.x;                      // 256
    for (int i = tid; i < 16 * 512; i += 256) Ws[i] = g_WE[i];
    for (int i = tid; i < 512; i += 256) cs[i] = g_c[i];
    int e0 = blockIdx.x * 64;
    for (int i = tid; i < 64 * 16; i += 256) {
        int r = i >> 4, k = i & 15;
        int e = e0 + r;
        efs[r][k] = (e < N_EDGES) ? ef[e * 16 + k] : 0.f;
    }
    __syncthreads();
    for (int r = 0; r < 64; r++) {
        int e = e0 + r;
        if (e >= N_EDGES) break;
        for (int j = tid; j < 512; j += 256) {
            float acc = cs[j];
            #pragma unroll
            for (int k = 0; k < 16; k++) acc = fmaf(efs[r][k], Ws[k * 512 + j], acc);
            g_E[(size_t)e * 512 + j] = acc;
        }
    }
}

// ---------------- degree histogram -----------------------------------------
__global__ void hist_k(const int* __restrict__ from, const int* __restrict__ to) {
    int i = blockIdx.x * 256 + threadIdx.x;
    if (i >= N_EDGES) return;
    atomicAdd(&g_degt[to[i]], 1);
    atomicAdd(&g_degf[from[i]], 1);
}

// ---------------- generic SGEMM:  C = [C +] relu( A@B + rowScale*bias ) -----
__global__ void __launch_bounds__(256) sgemm_k(
    const float* __restrict__ A, int lda,
    const float* __restrict__ B, int ldb,
    const float* __restrict__ bias,
    const int* __restrict__ rowScale,
    float* __restrict__ C, int ldc,
    int M, int N, int K, int flags)
{
    __shared__ __align__(16) float As[16][132];
    __shared__ __align__(16) float Bs[16][128];
    const int tid = threadIdx.x;
    const int m0 = blockIdx.x * 128;
    const int n0 = blockIdx.y * 128;
    const int tx = tid & 15;
    const int ty = tid >> 4;
    float acc[8][8];
    #pragma unroll
    for (int i = 0; i < 8; i++)
        #pragma unroll
        for (int j = 0; j < 8; j++) acc[i][j] = 0.f;

    const int aRow = tid >> 2;           // 0..63
    const int aCol = (tid & 3) << 2;     // 0,4,8,12
    const int bRow = tid >> 5;           // 0..7
    const int bCol = (tid & 31) << 2;

    for (int k0 = 0; k0 < K; k0 += 16) {
        #pragma unroll
        for (int hh = 0; hh < 2; hh++) {
            int m = m0 + aRow + hh * 64;
            float4 av = make_float4(0.f, 0.f, 0.f, 0.f);
            if (m < M) av = *(const float4*)(A + (size_t)m * lda + k0 + aCol);
            As[aCol + 0][aRow + hh * 64] = av.x;
            As[aCol + 1][aRow + hh * 64] = av.y;
            As[aCol + 2][aRow + hh * 64] = av.z;
            As[aCol + 3][aRow + hh * 64] = av.w;
        }
        #pragma unroll
        for (int hh = 0; hh < 2; hh++) {
            int kk = bRow + hh * 8;
            *(float4*)(&Bs[kk][bCol]) = *(const float4*)(B + (size_t)(k0 + kk) * ldb + n0 + bCol);
        }
        __syncthreads();
        #pragma unroll
        for (int k = 0; k < 16; k++) {
            float a[8], b[8];
            *(float4*)(a)     = *(const float4*)(&As[k][ty * 8]);
            *(float4*)(a + 4) = *(const float4*)(&As[k][ty * 8 + 4]);
            *(float4*)(b)     = *(const float4*)(&Bs[k][tx * 8]);
            *(float4*)(b + 4) = *(const float4*)(&Bs[k][tx * 8 + 4]);
            #pragma unroll
            for (int i = 0; i < 8; i++)
                #pragma unroll
                for (int j = 0; j < 8; j++)
                    acc[i][j] = fmaf(a[i], b[j], acc[i][j]);
        }
        __syncthreads();
    }

    #pragma unroll
    for (int i = 0; i < 8; i++) {
        int m = m0 + ty * 8 + i;
        if (m >= M) continue;
        float rs = rowScale ? (float)rowScale[m] : 1.f;
        #pragma unroll
        for (int j4 = 0; j4 < 8; j4 += 4) {
            int n = n0 + tx * 8 + j4;
            float4 v = make_float4(acc[i][j4], acc[i][j4 + 1], acc[i][j4 + 2], acc[i][j4 + 3]);
            if (bias) {
                v.x = fmaf(rs, bias[n + 0], v.x);
                v.y = fmaf(rs, bias[n + 1], v.y);
                v.z = fmaf(rs, bias[n + 2], v.z);
                v.w = fmaf(rs, bias[n + 3], v.w);
            }
            float* cp = C + (size_t)m * ldc + n;
            if (flags & FLAG_ADDC) {
                float4 c0 = *(const float4*)cp;
                v.x += c0.x; v.y += c0.y; v.z += c0.z; v.w += c0.w;
            }
            if (flags & FLAG_RELU) {
                v.x = fmaxf(v.x, 0.f); v.y = fmaxf(v.y, 0.f);
                v.z = fmaxf(v.z, 0.f); v.w = fmaxf(v.w, 0.f);
            }
            *(float4*)cp = v;
        }
    }
}

// ---------------- per-edge elementwise pass (one warp per edge) -------------
__global__ void edge_pass_k(const int* __restrict__ from, const int* __restrict__ to) {
    int warp = (blockIdx.x * 256 + threadIdx.x) >> 5;
    int lane = threadIdx.x & 31;
    if (warp >= N_EDGES) return;
    int f = from[warp], t = to[warp];
    const float4* E4 = (const float4*)(g_E + (size_t)warp * 512);
    const float4* Pf = (const float4*)(g_PQ + (size_t)f * 1024);
    const float4* Pt = (const float4*)(g_PQ + (size_t)t * 1024);
    float* Sm = g_S + (size_t)t * 512;
    float* Sr = g_S + (size_t)f * 512 + 256;
    #pragma unroll
    for (int s = 0; s < 2; s++) {
        int c = lane + 32 * s;                 // float4 column index 0..63
        // forward message hidden: relu(Pm[f] + Qm[t] + Em[edge]) -> segsum at t
        float4 e = E4[c], a = Pf[c], b = Pt[64 + c];
        float4 v;
        v.x = fmaxf(e.x + a.x + b.x, 0.f);
        v.y = fmaxf(e.y + a.y + b.y, 0.f);
        v.z = fmaxf(e.z + a.z + b.z, 0.f);
        v.w = fmaxf(e.w + a.w + b.w, 0.f);
        red_add_v4(Sm + 4 * c, v);
        // reverse message hidden: relu(Pr[t] + Qr[f] + Er[edge]) -> segsum at f
        float4 e2 = E4[64 + c], a2 = Pt[128 + c], b2 = Pf[192 + c];
        float4 v2;
        v2.x = fmaxf(e2.x + a2.x + b2.x, 0.f);
        v2.y = fmaxf(e2.y + a2.y + b2.y, 0.f);
        v2.z = fmaxf(e2.z + a2.z + b2.z, 0.f);
        v2.w = fmaxf(e2.w + a2.w + b2.w, 0.f);
        red_add_v4(Sr + 4 * c, v2);
    }
}

// copy h into X[:, 256:384]
__global__ void copyh_k() {
    int idx = blockIdx.x * 256 + threadIdx.x;   // N_NODES*32 float4
    if (idx >= N_NODES * 32) return;
    int n = idx >> 5, c = idx & 31;
    ((float4*)(g_X + (size_t)n * 384 + 256))[c] = ((const float4*)(g_h + (size_t)n * 128))[c];
}

// gated graph pooling: gv[graph] += sigmoid(g[:, :128]) * g[:, 128:]
__global__ void gate_k(const int* __restrict__ gidx) {
    int idx = blockIdx.x * 256 + threadIdx.x;   // N_NODES*32
    if (idx >= N_NODES * 32) return;
    int n = idx >> 5, c4 = (idx & 31) * 4;
    const float* gr = g_Hu + (size_t)n * 256;
    float4 a = *(const float4*)&gr[c4];
    float4 b = *(const float4*)&gr[128 + c4];
    float4 v;
    v.x = b.x / (1.f + expf(-a.x));
    v.y = b.y / (1.f + expf(-a.y));
    v.z = b.z / (1.f + expf(-a.z));
    v.w = b.w / (1.f + expf(-a.w));
    red_add_v4(&g_gv[gidx[n] * 128 + c4], v);
}

__global__ void gv2_k(const float* __restrict__ W, const float* __restrict__ b) {
    __shared__ float row[128];
    int r = blockIdx.x, d = threadIdx.x;        // 256 x 128
    row[d] = g_gv[r * 128 + d];
    __syncthreads();
    float acc = b[d];
    #pragma unroll 8
    for (int k = 0; k < 128; k++) acc = fmaf(row[k], W[k * 128 + d], acc);
    g_gv2[r * 128 + d] = acc;
}

__global__ void out_k(float* __restrict__ out) {
    __shared__ float sdata[128];
    int p = blockIdx.x, t = threadIdx.x;        // 128 x 128
    float dxy = g_gv2[(2 * p) * 128 + t] - g_gv2[(2 * p + 1) * 128 + t];
    sdata[t] = dxy * dxy;
    __syncthreads();
    for (int s = 64; s > 0; s >>= 1) {
        if (t < s) sdata[t] += sdata[t + s];
        __syncthreads();
    }
    if (t == 0) out[p] = -sdata[0];
}

// ---------------- host launch ----------------------------------------------
static void* sym(const void* s) { void* p = nullptr; cudaGetSymbolAddress(&p, s); return p; }

extern "C" void kernel_launch(void* const* d_in, const int* in_sizes, int n_in,
                              void* d_out, int out_size) {
    const float* nf     = (const float*)d_in[0];
    const float* ef     = (const float*)d_in[1];
    const int*   from   = (const int*)d_in[2];
    const int*   to     = (const int*)d_in[3];
    const int*   gidx   = (const int*)d_in[4];
    const float* enc_wn = (const float*)d_in[5];
    const float* enc_bn = (const float*)d_in[6];
    const float* enc_we = (const float*)d_in[7];
    const float* enc_be = (const float*)d_in[8];
    const float* msg_w1 = (const float*)d_in[9];
    const float* msg_b1 = (const float*)d_in[10];
    const float* msg_w2 = (const float*)d_in[11];
    const float* msg_b2 = (const float*)d_in[12];
    const float* rmsg_w1= (const float*)d_in[13];
    const float* rmsg_b1= (const float*)d_in[14];
    const float* rmsg_w2= (const float*)d_in[15];
    const float* rmsg_b2= (const float*)d_in[16];
    const float* upd_w1 = (const float*)d_in[17];
    const float* upd_b1 = (const float*)d_in[18];
    const float* upd_w2 = (const float*)d_in[19];
    const float* upd_b2 = (const float*)d_in[20];
    const float* agg_w1 = (const float*)d_in[21];
    const float* agg_b1 = (const float*)d_in[22];
    const float* agg_w2 = (const float*)d_in[23];
    const float* agg_b2 = (const float*)d_in[24];
    float* out = (float*)d_out;

    float* p_h    = (float*)sym(g_h);
    float* p_PQ   = (float*)sym(g_PQ);
    float* p_S    = (float*)sym(g_S);
    float* p_X    = (float*)sym(g_X);
    float* p_Hu   = (float*)sym(g_Hu);
    float* p_gv   = (float*)sym(g_gv);
    float* p_Wcat = (float*)sym(g_Wcat);
    int*   p_degt = (int*)sym(g_degt);
    int*   p_degf = (int*)sym(g_degf);

    const int GM = (N_NODES + 127) / 128;  // 235

    // one-time prep
    fold_k<<<1, 512>>>(enc_we, enc_be, msg_w1, msg_b1, rmsg_w1, rmsg_b1);
    wcat_k<<<512, 256>>>(msg_w1, rmsg_w1);
    zero_k<<<(N_NODES / 4 + 255) / 256, 256>>>((float4*)p_degt, N_NODES / 4);
    zero_k<<<(N_NODES / 4 + 255) / 256, 256>>>((float4*)p_degf, N_NODES / 4);
    hist_k<<<(N_EDGES + 255) / 256, 256>>>(from, to);
    enc_nodes_k<<<(N_NODES + 63) / 64, 256>>>(nf, enc_wn, enc_bn);
    enc_edges_k<<<(N_EDGES + 63) / 64, 256>>>(ef);

    for (int l = 0; l < NLAYERS; l++) {
        // PQ = h @ Wcat                       [30000,128] @ [128,1024]
        sgemm_k<<<dim3(GM, 8), 256>>>(p_h, 128, p_Wcat, 1024, nullptr, nullptr,
                                      p_PQ, 1024, N_NODES, 1024, 128, 0);
        // zero segment sums
        zero_k<<<(N_NODES * 128 + 255) / 256, 256>>>((float4*)p_S, N_NODES * 128);
        // elementwise edge pass + scatter
        edge_pass_k<<<N_EDGES / 8, 256>>>(from, to);
        // agg  = S[:, :256] @ msg_w2  + deg_to  * msg_b2   -> X[:, 0:128]
        sgemm_k<<<dim3(GM, 1), 256>>>(p_S, 512, msg_w2, 128, msg_b2, p_degt,
                                      p_X, 384, N_NODES, 128, 256, 0);
        // ragg = S[:, 256:] @ rmsg_w2 + deg_from * rmsg_b2 -> X[:, 128:256]
        sgemm_k<<<dim3(GM, 1), 256>>>(p_S + 256, 512, rmsg_w2, 128, rmsg_b2, p_degf,
                                      p_X + 128, 384, N_NODES, 128, 256, 0);
        // X[:, 256:384] = h
        copyh_k<<<(N_NODES * 32 + 255) / 256, 256>>>();
        // Hu = relu(X @ upd_w1 + b1)          [30000,384] @ [384,256]
        sgemm_k<<<dim3(GM, 2), 256>>>(p_X, 384, upd_w1, 256, upd_b1, nullptr,
                                      p_Hu, 256, N_NODES, 256, 384, FLAG_RELU);
        // h += Hu @ upd_w2 + b2               [30000,256] @ [256,128]
        sgemm_k<<<dim3(GM, 1), 256>>>(p_Hu, 256, upd_w2, 128, upd_b2, nullptr,
                                      p_h, 128, N_NODES, 128, 256, FLAG_ADDC);
    }

    // g = h @ agg_w1 + b1  (into g_Hu, [30000,256])
    sgemm_k<<<dim3(GM, 2), 256>>>(p_h, 128, agg_w1, 256, agg_b1, nullptr,
                                  p_Hu, 256, N_NODES, 256, 128, 0);
    zero_k<<<(N_GRAPHS * 32 + 255) / 256, 256>>>((float4*)p_gv, N_GRAPHS * 32);
    gate_k<<<(N_NODES * 32 + 255) / 256, 256>>>(gidx);
    gv2_k<<<N_GRAPHS, 128>>>(agg_w2, agg_b2);
    out_k<<<128, 128>>>(out);
    (void)in_sizes; (void)n_in; (void)out_size;
}